// round 8
// baseline (speedup 1.0000x reference)
#include <cuda_runtime.h>
#include <cuda_fp16.h>
#include <cstdint>

#define NTOK 2048
#define NG   32
#define DIN  1024
#define DHID 2048
#define DOUT 1024

// ---------------- scratch ----------------
__device__ __align__(1024) __half g_wA[(size_t)NG * 2 * DHID * DIN];   // [g][2h+s][k]  (s=0 gate, 1 up)
__device__ __align__(1024) __half g_wD[(size_t)NG * DOUT * DHID];      // [g][o][h]
__device__ __align__(1024) __half g_x16[(size_t)NTOK * NG * DIN];      // fp16 x
__device__ __align__(1024) __half g_hid[(size_t)NTOK * NG * DHID];     // fp16 hidden

// ---------------- PTX helpers ----------------
static __device__ __forceinline__ uint32_t smem_u32(const void* p) {
    uint32_t a;
    asm("{ .reg .u64 t; cvta.to.shared.u64 t, %1; cvt.u32.u64 %0, t; }" : "=r"(a) : "l"(p));
    return a;
}
#define CP_ASYNC16(dst, src) \
    asm volatile("cp.async.cg.shared.global [%0], [%1], 16;" :: "r"(dst), "l"(src))
#define CP_COMMIT() asm volatile("cp.async.commit_group;" ::: "memory")
#define CP_WAIT0()  asm volatile("cp.async.wait_group 0;" ::: "memory")

static __device__ __forceinline__ void ldsm4(uint32_t* r, uint32_t addr) {
    asm volatile("ldmatrix.sync.aligned.m8n8.x4.shared.b16 {%0,%1,%2,%3}, [%4];"
                 : "=r"(r[0]), "=r"(r[1]), "=r"(r[2]), "=r"(r[3]) : "r"(addr));
}
static __device__ __forceinline__ void mma16816(float* c, const uint32_t* a,
                                                uint32_t b0, uint32_t b1) {
    asm volatile(
        "mma.sync.aligned.m16n8k16.row.col.f32.f16.f16.f32 "
        "{%0,%1,%2,%3}, {%4,%5,%6,%7}, {%8,%9}, {%0,%1,%2,%3};"
        : "+f"(c[0]), "+f"(c[1]), "+f"(c[2]), "+f"(c[3])
        : "r"(a[0]), "r"(a[1]), "r"(a[2]), "r"(a[3]), "r"(b0), "r"(b1));
}

// ---------------- prepass kernels (round-6 proven) ----------------
__global__ void prep_gateup(const float* __restrict__ gw, const float* __restrict__ uw) {
    __shared__ float tg[32][33];
    __shared__ float tu[32][33];
    int g = blockIdx.z, k0 = blockIdx.x * 32, h0 = blockIdx.y * 32;
    int tx = threadIdx.x, ty = threadIdx.y;
    const float* gp = gw + ((size_t)g * DIN + k0) * DHID + h0;
    const float* up = uw + ((size_t)g * DIN + k0) * DHID + h0;
#pragma unroll
    for (int i = 0; i < 4; ++i) {
        int k = ty + i * 8;
        tg[k][tx] = gp[(size_t)k * DHID + tx];
        tu[k][tx] = up[(size_t)k * DHID + tx];
    }
    __syncthreads();
#pragma unroll
    for (int i = 0; i < 4; ++i) {
        int hh = ty + i * 8;
        size_t row = ((size_t)g * 2 * DHID + 2 * (size_t)(h0 + hh)) * DIN + k0;
        g_wA[row + tx]       = __float2half(tg[tx][hh]);
        g_wA[row + DIN + tx] = __float2half(tu[tx][hh]);
    }
}

__global__ void prep_down(const float* __restrict__ dw) {
    __shared__ float t[32][33];
    int g = blockIdx.z, h0 = blockIdx.x * 32, o0 = blockIdx.y * 32;
    int tx = threadIdx.x, ty = threadIdx.y;
    const float* dp = dw + ((size_t)g * DHID + h0) * DOUT + o0;
#pragma unroll
    for (int i = 0; i < 4; ++i) {
        int h = ty + i * 8;
        t[h][tx] = dp[(size_t)h * DOUT + tx];
    }
    __syncthreads();
#pragma unroll
    for (int i = 0; i < 4; ++i) {
        int oo = ty + i * 8;
        g_wD[((size_t)g * DOUT + o0 + oo) * DHID + h0 + tx] = __float2half(t[tx][oo]);
    }
}

__global__ void prep_x(const float* __restrict__ x) {
    size_t i = (size_t)blockIdx.x * blockDim.x + threadIdx.x;
    float4 v = reinterpret_cast<const float4*>(x)[i];
    __half2 a = __floats2half2_rn(v.x, v.y);
    __half2 b = __floats2half2_rn(v.z, v.w);
    uint2 o;
    o.x = *reinterpret_cast<uint32_t*>(&a);
    o.y = *reinterpret_cast<uint32_t*>(&b);
    reinterpret_cast<uint2*>(g_x16)[i] = o;
}

// ---------------- GEMM ----------------
// CTA tile M=128 x N=128, 256 threads (8 warps, 2x4), warp tile 64x32.
// K-step 64, 3-stage ring, 2 CTAs/SM. Cross-iteration fragment prefetch:
// wait_group 0 + barrier makes stages c AND c+1 visible, so next iter's kk=0
// frags load BEFORE the next barrier -> no post-barrier LDSM stall.
#define A_BYTES   (128u * 128u)           // 16384
#define B_BYTES   (128u * 128u)           // 16384
#define STAGE_B   (A_BYTES + B_BYTES)     // 32768
#define SMEM_BYTES (3u * STAGE_B)         // 98304 per CTA -> 192KB for 2 CTAs

static __device__ __forceinline__ void load_stage(uint32_t sb, int s,
        const __half* __restrict__ A, int lda,
        const __half* __restrict__ B, int ldb, int k0, int tid) {
    uint32_t abase = sb + (uint32_t)s * STAGE_B;
#pragma unroll
    for (int i = 0; i < 4; ++i) {                 // A: 128 rows x 8 chunks(16B)
        int id = tid + (i << 8);
        int r = id >> 3, c = id & 7;
        uint32_t dst = abase + (uint32_t)r * 128u + (uint32_t)(((c ^ (r & 7)) << 4));
        CP_ASYNC16(dst, A + (size_t)r * lda + k0 + c * 8);
    }
    uint32_t bbase = abase + A_BYTES;
#pragma unroll
    for (int i = 0; i < 4; ++i) {                 // B: 128 rows x 8 chunks
        int id = tid + (i << 8);
        int r = id >> 3, c = id & 7;
        uint32_t dst = bbase + (uint32_t)r * 128u + (uint32_t)(((c ^ (r & 7)) << 4));
        CP_ASYNC16(dst, B + (size_t)r * ldb + k0 + c * 8);
    }
}

template<bool PHASE1>
__global__ __launch_bounds__(256, 2) void gemm_kernel(float* __restrict__ outp) {
    constexpr int KTOT = PHASE1 ? DIN : DHID;
    constexpr int NC   = KTOT / 64;
    constexpr int LDA  = NG * KTOT;

    extern __shared__ __align__(1024) char smem[];
    uint32_t sb = smem_u32(smem);
    int tid  = threadIdx.x;
    int wid  = tid >> 5;
    int lane = tid & 31;
    int wm   = wid >> 2;          // 0..1  (64-row block)
    int wn   = wid & 3;           // 0..3  (32-col block)
    int m0   = blockIdx.x * 128;
    int g    = blockIdx.z;

    const __half* Abase = (PHASE1 ? g_x16 : g_hid)
                        + (size_t)m0 * LDA + (size_t)g * KTOT;
    const __half* Bbase = (PHASE1 ? g_wA : g_wD)
                        + (size_t)g * (PHASE1 ? (size_t)2 * DHID * DIN : (size_t)DOUT * DHID)
                        + (size_t)blockIdx.y * 128 * KTOT;

    // Precomputed swizzled ldmatrix offsets: addr = stagebase + (pre ^ (ch<<4))
    uint32_t preA[4], preB[2];
    {
        int rsel = lane & 15;
        int hi   = (lane >> 4) << 4;
#pragma unroll
        for (int mt = 0; mt < 4; ++mt) {
            int row = wm * 64 + mt * 16 + rsel;
            preA[mt] = (uint32_t)row * 128u + (uint32_t)(((row & 7) << 4) ^ hi);
        }
#pragma unroll
        for (int nt = 0; nt < 2; ++nt) {
            int row = wn * 32 + nt * 16 + rsel;
            preB[nt] = (uint32_t)row * 128u + (uint32_t)(((row & 7) << 4) ^ hi);
        }
    }

    float acc[4][4][4];
#pragma unroll
    for (int a = 0; a < 4; ++a)
#pragma unroll
        for (int b = 0; b < 4; ++b)
#pragma unroll
            for (int c = 0; c < 4; ++c) acc[a][b][c] = 0.f;

    // prologue: commit stages 0 and 1
    load_stage(sb, 0, Abase, LDA, Bbase, KTOT, 0, tid);
    CP_COMMIT();
    load_stage(sb, 1, Abase, LDA, Bbase, KTOT, 64, tid);
    CP_COMMIT();

    uint32_t af[4][4], bf[2][4];   // single fragment set, persists across barrier
    int st = 0;
#pragma unroll 1
    for (int c = 0; c < NC; ++c) {
        // Only L(c+1) can be pending here (L(c+2) not yet committed) -> WAIT0 is
        // exactly "L(c+1) landed". Barrier then makes stages c AND c+1 CTA-visible.
        CP_WAIT0();
        __syncthreads();
        uint32_t abase = sb + (uint32_t)st * STAGE_B;
        uint32_t bbase = abase + A_BYTES;

        if (c == 0) {    // one-time initial fragment load (later iters prefetch)
#pragma unroll
            for (int mt = 0; mt < 4; ++mt) ldsm4(af[mt], abase + preA[mt]);
#pragma unroll
            for (int nt = 0; nt < 2; ++nt) ldsm4(bf[nt], bbase + preB[nt]);
        }

        if (c + 2 < NC) {
            int st2 = (st == 0) ? 2 : st - 1;
            load_stage(sb, st2, Abase, LDA, Bbase, KTOT, (c + 2) * 64, tid);
            CP_COMMIT();
        }

#pragma unroll
        for (int kk = 0; kk < 4; ++kk) {
            // MMA with current fragments
#pragma unroll
            for (int mt = 0; mt < 4; ++mt)
#pragma unroll
                for (int n8 = 0; n8 < 4; ++n8)
                    mma16816(acc[mt][n8], af[mt],
                             bf[n8 >> 1][n8 & 1], bf[n8 >> 1][2 + (n8 & 1)]);
            // load fragments for next kk (same stage) or next iter's kk=0 (stage c+1)
            if (kk < 3) {
                uint32_t x = (uint32_t)((kk + 1) << 5);
#pragma unroll
                for (int mt = 0; mt < 4; ++mt) ldsm4(af[mt], abase + (preA[mt] ^ x));
#pragma unroll
                for (int nt = 0; nt < 2; ++nt) ldsm4(bf[nt], bbase + (preB[nt] ^ x));
            } else if (c + 1 < NC) {
                int stn = (st == 2) ? 0 : st + 1;
                uint32_t ab2 = sb + (uint32_t)stn * STAGE_B;
                uint32_t bb2 = ab2 + A_BYTES;
#pragma unroll
                for (int mt = 0; mt < 4; ++mt) ldsm4(af[mt], ab2 + preA[mt]);
#pragma unroll
                for (int nt = 0; nt < 2; ++nt) ldsm4(bf[nt], bb2 + preB[nt]);
            }
        }
        st = (st == 2) ? 0 : st + 1;
    }

    // ---- epilogue ----
    if constexpr (PHASE1) {
        __syncthreads();
        __half* sh = reinterpret_cast<__half*>(smem);   // staging [128][72]
#pragma unroll
        for (int mt = 0; mt < 4; ++mt)
#pragma unroll
            for (int n8 = 0; n8 < 4; ++n8) {
                int r0 = wm * 64 + mt * 16 + (lane >> 2);
                int hl = wn * 16 + n8 * 4 + (lane & 3);
                float* cc = acc[mt][n8];
                float gv0 = cc[0], uv0 = cc[1];
                float gv1 = cc[2], uv1 = cc[3];
                float h0 = uv0 * gv0 / (1.f + __expf(-gv0));
                float h1 = uv1 * gv1 / (1.f + __expf(-gv1));
                sh[(size_t)r0 * 72 + hl]       = __float2half(h0);
                sh[(size_t)(r0 + 8) * 72 + hl] = __float2half(h1);
            }
        __syncthreads();
        // copy out: 128 rows x 64 halves
        __half* optr = g_hid + (size_t)m0 * (NG * DHID) + (size_t)g * DHID
                     + (size_t)blockIdx.y * 64;
#pragma unroll
        for (int p = 0; p < 4; ++p) {
            int row = (tid >> 3) + p * 32;
            int ch  = tid & 7;
            uint4 v = *reinterpret_cast<uint4*>(sh + (size_t)row * 72 + ch * 8);
            *reinterpret_cast<uint4*>(optr + (size_t)row * (NG * DHID) + ch * 8) = v;
        }
    } else {
#pragma unroll
        for (int mt = 0; mt < 4; ++mt)
#pragma unroll
            for (int n8 = 0; n8 < 4; ++n8) {
                int r0  = wm * 64 + mt * 16 + (lane >> 2);
                int col = blockIdx.y * 128 + wn * 32 + n8 * 8 + (lane & 3) * 2;
                float* cc = acc[mt][n8];
                float* p0 = outp + ((size_t)(m0 + r0) * NG + g) * DOUT + col;
                float* p1 = outp + ((size_t)(m0 + r0 + 8) * NG + g) * DOUT + col;
                *reinterpret_cast<float2*>(p0) = make_float2(cc[0], cc[1]);
                *reinterpret_cast<float2*>(p1) = make_float2(cc[2], cc[3]);
            }
    }
}

// ---------------- launch ----------------
extern "C" void kernel_launch(void* const* d_in, const int* in_sizes, int n_in,
                              void* d_out, int out_size) {
    (void)in_sizes; (void)n_in; (void)out_size;
    const float* x  = (const float*)d_in[0];
    const float* gw = (const float*)d_in[1];
    const float* uw = (const float*)d_in[2];
    const float* dw = (const float*)d_in[3];
    float* out = (float*)d_out;

    cudaFuncSetAttribute(gemm_kernel<true>,  cudaFuncAttributeMaxDynamicSharedMemorySize, SMEM_BYTES);
    cudaFuncSetAttribute(gemm_kernel<false>, cudaFuncAttributeMaxDynamicSharedMemorySize, SMEM_BYTES);

    dim3 tb32x8(32, 8);
    prep_gateup<<<dim3(DIN / 32, DHID / 32, NG), tb32x8>>>(gw, uw);
    prep_down<<<dim3(DHID / 32, DOUT / 32, NG), tb32x8>>>(dw);
    prep_x<<<65536, 256>>>(x);

    // GEMM1: grid 16 m-tiles x 32 n-tiles x 32 groups
    gemm_kernel<true><<<dim3(16, 32, NG), 256, SMEM_BYTES>>>(out);
    // GEMM2: grid 16 m-tiles x 8 n-tiles x 32 groups
    gemm_kernel<false><<<dim3(16, 8, NG), 256, SMEM_BYTES>>>(out);
}

// round 10
// speedup vs baseline: 1.0465x; 1.0465x over previous
#include <cuda_runtime.h>
#include <cuda_fp16.h>
#include <cstdint>

#define NTOK 2048
#define NG   32
#define DIN  1024
#define DHID 2048
#define DOUT 1024

// ---------------- scratch ----------------
__device__ __align__(1024) __half g_wA[(size_t)NG * 2 * DHID * DIN];   // [g][2h+s][k]  (s=0 gate, 1 up)
__device__ __align__(1024) __half g_wD[(size_t)NG * DOUT * DHID];      // [g][o][h]
__device__ __align__(1024) __half g_x16[(size_t)NTOK * NG * DIN];      // fp16 x
__device__ __align__(1024) __half g_hid[(size_t)NTOK * NG * DHID];     // fp16 hidden

// ---------------- PTX helpers ----------------
static __device__ __forceinline__ uint32_t smem_u32(const void* p) {
    uint32_t a;
    asm("{ .reg .u64 t; cvta.to.shared.u64 t, %1; cvt.u32.u64 %0, t; }" : "=r"(a) : "l"(p));
    return a;
}
#define CP_ASYNC16(dst, src) \
    asm volatile("cp.async.cg.shared.global [%0], [%1], 16;" :: "r"(dst), "l"(src))
#define CP_COMMIT() asm volatile("cp.async.commit_group;" ::: "memory")
#define CP_WAIT1()  asm volatile("cp.async.wait_group 1;" ::: "memory")
#define CP_WAIT0()  asm volatile("cp.async.wait_group 0;" ::: "memory")

static __device__ __forceinline__ void ldsm4(uint32_t* r, uint32_t addr) {
    asm volatile("ldmatrix.sync.aligned.m8n8.x4.shared.b16 {%0,%1,%2,%3}, [%4];"
                 : "=r"(r[0]), "=r"(r[1]), "=r"(r[2]), "=r"(r[3]) : "r"(addr));
}
static __device__ __forceinline__ void mma16816(float* c, const uint32_t* a,
                                                uint32_t b0, uint32_t b1) {
    asm volatile(
        "mma.sync.aligned.m16n8k16.row.col.f32.f16.f16.f32 "
        "{%0,%1,%2,%3}, {%4,%5,%6,%7}, {%8,%9}, {%0,%1,%2,%3};"
        : "+f"(c[0]), "+f"(c[1]), "+f"(c[2]), "+f"(c[3])
        : "r"(a[0]), "r"(a[1]), "r"(a[2]), "r"(a[3]), "r"(b0), "r"(b1));
}

// ---------------- prepass kernels (round-6 proven) ----------------
__global__ void prep_gateup(const float* __restrict__ gw, const float* __restrict__ uw) {
    __shared__ float tg[32][33];
    __shared__ float tu[32][33];
    int g = blockIdx.z, k0 = blockIdx.x * 32, h0 = blockIdx.y * 32;
    int tx = threadIdx.x, ty = threadIdx.y;
    const float* gp = gw + ((size_t)g * DIN + k0) * DHID + h0;
    const float* up = uw + ((size_t)g * DIN + k0) * DHID + h0;
#pragma unroll
    for (int i = 0; i < 4; ++i) {
        int k = ty + i * 8;
        tg[k][tx] = gp[(size_t)k * DHID + tx];
        tu[k][tx] = up[(size_t)k * DHID + tx];
    }
    __syncthreads();
#pragma unroll
    for (int i = 0; i < 4; ++i) {
        int hh = ty + i * 8;
        size_t row = ((size_t)g * 2 * DHID + 2 * (size_t)(h0 + hh)) * DIN + k0;
        g_wA[row + tx]       = __float2half(tg[tx][hh]);
        g_wA[row + DIN + tx] = __float2half(tu[tx][hh]);
    }
}

__global__ void prep_down(const float* __restrict__ dw) {
    __shared__ float t[32][33];
    int g = blockIdx.z, h0 = blockIdx.x * 32, o0 = blockIdx.y * 32;
    int tx = threadIdx.x, ty = threadIdx.y;
    const float* dp = dw + ((size_t)g * DHID + h0) * DOUT + o0;
#pragma unroll
    for (int i = 0; i < 4; ++i) {
        int h = ty + i * 8;
        t[h][tx] = dp[(size_t)h * DOUT + tx];
    }
    __syncthreads();
#pragma unroll
    for (int i = 0; i < 4; ++i) {
        int oo = ty + i * 8;
        g_wD[((size_t)g * DOUT + o0 + oo) * DHID + h0 + tx] = __float2half(t[tx][oo]);
    }
}

__global__ void prep_x(const float* __restrict__ x) {
    size_t i = (size_t)blockIdx.x * blockDim.x + threadIdx.x;
    float4 v = reinterpret_cast<const float4*>(x)[i];
    __half2 a = __floats2half2_rn(v.x, v.y);
    __half2 b = __floats2half2_rn(v.z, v.w);
    uint2 o;
    o.x = *reinterpret_cast<uint32_t*>(&a);
    o.y = *reinterpret_cast<uint32_t*>(&b);
    reinterpret_cast<uint2*>(g_x16)[i] = o;
}

// ---------------- GEMM ----------------
// CTA tile M=128 x N=128, 256 threads (8 warps, 2x4), warp tile 64x32.
// K-step 64, 3-stage ring, 2 CTAs/SM. Corrected cross-iteration fragment
// prefetch: commit BEFORE wait1 so L(c+1) is landed while L(c+2) stays in
// flight; two barriers per iter (WAR guard + visibility).
#define A_BYTES   (128u * 128u)           // 16384
#define B_BYTES   (128u * 128u)           // 16384
#define STAGE_B   (A_BYTES + B_BYTES)     // 32768
#define SMEM_BYTES (3u * STAGE_B)         // 98304 per CTA -> 192KB for 2 CTAs

static __device__ __forceinline__ void load_stage(uint32_t sb, int s,
        const __half* __restrict__ A, int lda,
        const __half* __restrict__ B, int ldb, int k0, int tid) {
    uint32_t abase = sb + (uint32_t)s * STAGE_B;
#pragma unroll
    for (int i = 0; i < 4; ++i) {                 // A: 128 rows x 8 chunks(16B)
        int id = tid + (i << 8);
        int r = id >> 3, c = id & 7;
        uint32_t dst = abase + (uint32_t)r * 128u + (uint32_t)(((c ^ (r & 7)) << 4));
        CP_ASYNC16(dst, A + (size_t)r * lda + k0 + c * 8);
    }
    uint32_t bbase = abase + A_BYTES;
#pragma unroll
    for (int i = 0; i < 4; ++i) {                 // B: 128 rows x 8 chunks
        int id = tid + (i << 8);
        int r = id >> 3, c = id & 7;
        uint32_t dst = bbase + (uint32_t)r * 128u + (uint32_t)(((c ^ (r & 7)) << 4));
        CP_ASYNC16(dst, B + (size_t)r * ldb + k0 + c * 8);
    }
}

template<bool PHASE1>
__global__ __launch_bounds__(256, 2) void gemm_kernel(float* __restrict__ outp) {
    constexpr int KTOT = PHASE1 ? DIN : DHID;
    constexpr int NC   = KTOT / 64;
    constexpr int LDA  = NG * KTOT;

    extern __shared__ __align__(1024) char smem[];
    uint32_t sb = smem_u32(smem);
    int tid  = threadIdx.x;
    int wid  = tid >> 5;
    int lane = tid & 31;
    int wm   = wid >> 2;          // 0..1  (64-row block)
    int wn   = wid & 3;           // 0..3  (32-col block)
    int m0   = blockIdx.x * 128;
    int g    = blockIdx.z;

    const __half* Abase = (PHASE1 ? g_x16 : g_hid)
                        + (size_t)m0 * LDA + (size_t)g * KTOT;
    const __half* Bbase = (PHASE1 ? g_wA : g_wD)
                        + (size_t)g * (PHASE1 ? (size_t)2 * DHID * DIN : (size_t)DOUT * DHID)
                        + (size_t)blockIdx.y * 128 * KTOT;

    // Precomputed swizzled ldmatrix offsets: addr = stagebase + (pre ^ (ch<<4))
    uint32_t preA[4], preB[2];
    {
        int rsel = lane & 15;
        int hi   = (lane >> 4) << 4;
#pragma unroll
        for (int mt = 0; mt < 4; ++mt) {
            int row = wm * 64 + mt * 16 + rsel;
            preA[mt] = (uint32_t)row * 128u + (uint32_t)(((row & 7) << 4) ^ hi);
        }
#pragma unroll
        for (int nt = 0; nt < 2; ++nt) {
            int row = wn * 32 + nt * 16 + rsel;
            preB[nt] = (uint32_t)row * 128u + (uint32_t)(((row & 7) << 4) ^ hi);
        }
    }

    float acc[4][4][4];
#pragma unroll
    for (int a = 0; a < 4; ++a)
#pragma unroll
        for (int b = 0; b < 4; ++b)
#pragma unroll
            for (int c = 0; c < 4; ++c) acc[a][b][c] = 0.f;

    // prologue: commit stages 0,1; make stage 0 visible; preload kk=0 fragments
    load_stage(sb, 0, Abase, LDA, Bbase, KTOT, 0, tid);
    CP_COMMIT();
    load_stage(sb, 1, Abase, LDA, Bbase, KTOT, 64, tid);
    CP_COMMIT();
    CP_WAIT1();                   // L0 landed (L1 in flight)
    __syncthreads();              // L0 visible

    uint32_t af[4][4], bf[2][4];  // fragments persist across barriers
#pragma unroll
    for (int mt = 0; mt < 4; ++mt) ldsm4(af[mt], sb + preA[mt]);
#pragma unroll
    for (int nt = 0; nt < 2; ++nt) ldsm4(bf[nt], sb + A_BYTES + preB[nt]);

    int st = 0;
#pragma unroll 1
    for (int c = 0; c < NC; ++c) {
        // barrier A: every thread done reading slot (c+2)%3 (== stage c-1's slot)
        __syncthreads();
        if (c + 2 < NC) {
            int st2 = (st == 0) ? 2 : st - 1;     // (c+2)%3
            load_stage(sb, st2, Abase, LDA, Bbase, KTOT, (c + 2) * 64, tid);
            CP_COMMIT();
            CP_WAIT1();           // pending {L(c+1), L(c+2)} -> L(c+1) landed
        } else {
            CP_WAIT0();           // tail: drain everything (nothing left in flight)
        }
        // barrier B: L(c+1) visible to all threads
        __syncthreads();

        uint32_t abase = sb + (uint32_t)st * STAGE_B;
        uint32_t bbase = abase + A_BYTES;
        int stn = (st == 2) ? 0 : st + 1;
        uint32_t nabase = sb + (uint32_t)stn * STAGE_B;
        uint32_t nbbase = nabase + A_BYTES;

#pragma unroll
        for (int kk = 0; kk < 4; ++kk) {
            // MMA with current fragments (loaded before barrier B)
#pragma unroll
            for (int mt = 0; mt < 4; ++mt)
#pragma unroll
                for (int n8 = 0; n8 < 4; ++n8)
                    mma16816(acc[mt][n8], af[mt],
                             bf[n8 >> 1][n8 & 1], bf[n8 >> 1][2 + (n8 & 1)]);
            if (kk < 3) {
                uint32_t x = (uint32_t)((kk + 1) << 5);
#pragma unroll
                for (int mt = 0; mt < 4; ++mt) ldsm4(af[mt], abase + (preA[mt] ^ x));
#pragma unroll
                for (int nt = 0; nt < 2; ++nt) ldsm4(bf[nt], bbase + (preB[nt] ^ x));
            } else if (c + 1 < NC) {
                // prefetch next iteration's kk=0 fragments from stage c+1
#pragma unroll
                for (int mt = 0; mt < 4; ++mt) ldsm4(af[mt], nabase + preA[mt]);
#pragma unroll
                for (int nt = 0; nt < 2; ++nt) ldsm4(bf[nt], nbbase + preB[nt]);
            }
        }
        st = stn;
    }

    // ---- epilogue ----
    if constexpr (PHASE1) {
        __syncthreads();
        __half* sh = reinterpret_cast<__half*>(smem);   // staging [128][72]
#pragma unroll
        for (int mt = 0; mt < 4; ++mt)
#pragma unroll
            for (int n8 = 0; n8 < 4; ++n8) {
                int r0 = wm * 64 + mt * 16 + (lane >> 2);
                int hl = wn * 16 + n8 * 4 + (lane & 3);
                float* cc = acc[mt][n8];
                float gv0 = cc[0], uv0 = cc[1];
                float gv1 = cc[2], uv1 = cc[3];
                float h0 = uv0 * gv0 / (1.f + __expf(-gv0));
                float h1 = uv1 * gv1 / (1.f + __expf(-gv1));
                sh[(size_t)r0 * 72 + hl]       = __float2half(h0);
                sh[(size_t)(r0 + 8) * 72 + hl] = __float2half(h1);
            }
        __syncthreads();
        // copy out: 128 rows x 64 halves
        __half* optr = g_hid + (size_t)m0 * (NG * DHID) + (size_t)g * DHID
                     + (size_t)blockIdx.y * 64;
#pragma unroll
        for (int p = 0; p < 4; ++p) {
            int row = (tid >> 3) + p * 32;
            int ch  = tid & 7;
            uint4 v = *reinterpret_cast<uint4*>(sh + (size_t)row * 72 + ch * 8);
            *reinterpret_cast<uint4*>(optr + (size_t)row * (NG * DHID) + ch * 8) = v;
        }
    } else {
#pragma unroll
        for (int mt = 0; mt < 4; ++mt)
#pragma unroll
            for (int n8 = 0; n8 < 4; ++n8) {
                int r0  = wm * 64 + mt * 16 + (lane >> 2);
                int col = blockIdx.y * 128 + wn * 32 + n8 * 8 + (lane & 3) * 2;
                float* cc = acc[mt][n8];
                float* p0 = outp + ((size_t)(m0 + r0) * NG + g) * DOUT + col;
                float* p1 = outp + ((size_t)(m0 + r0 + 8) * NG + g) * DOUT + col;
                *reinterpret_cast<float2*>(p0) = make_float2(cc[0], cc[1]);
                *reinterpret_cast<float2*>(p1) = make_float2(cc[2], cc[3]);
            }
    }
}

// ---------------- launch ----------------
extern "C" void kernel_launch(void* const* d_in, const int* in_sizes, int n_in,
                              void* d_out, int out_size) {
    (void)in_sizes; (void)n_in; (void)out_size;
    const float* x  = (const float*)d_in[0];
    const float* gw = (const float*)d_in[1];
    const float* uw = (const float*)d_in[2];
    const float* dw = (const float*)d_in[3];
    float* out = (float*)d_out;

    cudaFuncSetAttribute(gemm_kernel<true>,  cudaFuncAttributeMaxDynamicSharedMemorySize, SMEM_BYTES);
    cudaFuncSetAttribute(gemm_kernel<false>, cudaFuncAttributeMaxDynamicSharedMemorySize, SMEM_BYTES);

    dim3 tb32x8(32, 8);
    prep_gateup<<<dim3(DIN / 32, DHID / 32, NG), tb32x8>>>(gw, uw);
    prep_down<<<dim3(DHID / 32, DOUT / 32, NG), tb32x8>>>(dw);
    prep_x<<<65536, 256>>>(x);

    // GEMM1: grid 16 m-tiles x 32 n-tiles x 32 groups
    gemm_kernel<true><<<dim3(16, 32, NG), 256, SMEM_BYTES>>>(out);
    // GEMM2: grid 16 m-tiles x 8 n-tiles x 32 groups
    gemm_kernel<false><<<dim3(16, 8, NG), 256, SMEM_BYTES>>>(out);
}

// round 11
// speedup vs baseline: 1.0618x; 1.0146x over previous
#include <cuda_runtime.h>
#include <cuda_fp16.h>
#include <cstdint>

#define NTOK 2048
#define NG   32
#define DIN  1024
#define DHID 2048
#define DOUT 1024

// ---------------- scratch ----------------
__device__ __align__(1024) __half g_wA[(size_t)NG * 2 * DHID * DIN];   // [g][2h+s][k]  (s=0 gate, 1 up)
__device__ __align__(1024) __half g_wD[(size_t)NG * DOUT * DHID];      // [g][o][h]
__device__ __align__(1024) __half g_x16[(size_t)NTOK * NG * DIN];      // fp16 x
__device__ __align__(1024) __half g_hid[(size_t)NTOK * NG * DHID];     // fp16 hidden

// ---------------- PTX helpers ----------------
static __device__ __forceinline__ uint32_t smem_u32(const void* p) {
    uint32_t a;
    asm("{ .reg .u64 t; cvta.to.shared.u64 t, %1; cvt.u32.u64 %0, t; }" : "=r"(a) : "l"(p));
    return a;
}
#define CP_ASYNC16(dst, src) \
    asm volatile("cp.async.cg.shared.global [%0], [%1], 16;" :: "r"(dst), "l"(src))
#define CP_COMMIT() asm volatile("cp.async.commit_group;" ::: "memory")
#define CP_WAIT1()  asm volatile("cp.async.wait_group 1;" ::: "memory")

static __device__ __forceinline__ void ldsm4(uint32_t* r, uint32_t addr) {
    asm volatile("ldmatrix.sync.aligned.m8n8.x4.shared.b16 {%0,%1,%2,%3}, [%4];"
                 : "=r"(r[0]), "=r"(r[1]), "=r"(r[2]), "=r"(r[3]) : "r"(addr));
}
static __device__ __forceinline__ void mma16816(float* c, const uint32_t* a,
                                                uint32_t b0, uint32_t b1) {
    asm volatile(
        "mma.sync.aligned.m16n8k16.row.col.f32.f16.f16.f32 "
        "{%0,%1,%2,%3}, {%4,%5,%6,%7}, {%8,%9}, {%0,%1,%2,%3};"
        : "+f"(c[0]), "+f"(c[1]), "+f"(c[2]), "+f"(c[3])
        : "r"(a[0]), "r"(a[1]), "r"(a[2]), "r"(a[3]), "r"(b0), "r"(b1));
}

// ---------------- prepass kernels (rewritten: full-line stores) ----------------
// gate/up [G,DIN,DHID] fp32 -> g_wA [G][2h+s][k] fp16.
// Tile: 64 k x 32 h, 256 threads. 128B coalesced loads AND 128B stores.
__global__ __launch_bounds__(256) void prep_gateup(const float* __restrict__ gw,
                                                   const float* __restrict__ uw) {
    __shared__ float sg[64][33];
    __shared__ float su[64][33];
    int g = blockIdx.z, k0 = blockIdx.x * 64, h0 = blockIdx.y * 32;
    int tid = threadIdx.x;
    const float* gp = gw + ((size_t)g * DIN + k0) * DHID + h0;
    const float* up = uw + ((size_t)g * DIN + k0) * DHID + h0;

    // load: 64 k-rows x 8 float4 chunks (32 floats of h) = 512 slots, 2 iters
#pragma unroll
    for (int it = 0; it < 2; ++it) {
        int slot = tid + it * 256;
        int k = slot >> 3, c = slot & 7;
        float4 vg = *reinterpret_cast<const float4*>(gp + (size_t)k * DHID + c * 4);
        float4 vu = *reinterpret_cast<const float4*>(up + (size_t)k * DHID + c * 4);
        sg[k][c * 4 + 0] = vg.x; sg[k][c * 4 + 1] = vg.y;
        sg[k][c * 4 + 2] = vg.z; sg[k][c * 4 + 3] = vg.w;
        su[k][c * 4 + 0] = vu.x; su[k][c * 4 + 1] = vu.y;
        su[k][c * 4 + 2] = vu.z; su[k][c * 4 + 3] = vu.w;
    }
    __syncthreads();

    // store: 32 h x 2 s x 8 chunks (8 halves each) = 512 slots, 2 iters
#pragma unroll
    for (int it = 0; it < 2; ++it) {
        int slot  = tid + it * 256;
        int h     = slot & 31;
        int s     = (slot >> 5) & 1;
        int chunk = slot >> 6;             // 0..7 -> k_local = chunk*8 + j
        const float (*src)[33] = s ? su : sg;
        __half2 hh[4];
#pragma unroll
        for (int j = 0; j < 4; ++j)
            hh[j] = __floats2half2_rn(src[chunk * 8 + 2 * j][h],
                                      src[chunk * 8 + 2 * j + 1][h]);
        size_t row = ((size_t)g * 2 * DHID + 2 * (size_t)(h0 + h) + s) * DIN + k0;
        *reinterpret_cast<uint4*>(&g_wA[row + chunk * 8]) =
            make_uint4(*reinterpret_cast<uint32_t*>(&hh[0]),
                       *reinterpret_cast<uint32_t*>(&hh[1]),
                       *reinterpret_cast<uint32_t*>(&hh[2]),
                       *reinterpret_cast<uint32_t*>(&hh[3]));
    }
}

// down_w [G,DHID,DOUT] fp32 -> g_wD [G][o][h] fp16. Tile: 64 h x 64 o.
__global__ __launch_bounds__(256) void prep_down(const float* __restrict__ dw) {
    __shared__ float t[64][65];
    int g = blockIdx.z, h0 = blockIdx.x * 64, o0 = blockIdx.y * 64;
    int tid = threadIdx.x;
    const float* dp = dw + ((size_t)g * DHID + h0) * DOUT + o0;

    // load: 64 h-rows x 16 float4 chunks (64 floats of o) = 1024 slots, 4 iters
#pragma unroll
    for (int it = 0; it < 4; ++it) {
        int slot = tid + it * 256;
        int hh = slot >> 4, c = slot & 15;
        float4 v = *reinterpret_cast<const float4*>(dp + (size_t)hh * DOUT + c * 4);
        t[hh][c * 4 + 0] = v.x; t[hh][c * 4 + 1] = v.y;
        t[hh][c * 4 + 2] = v.z; t[hh][c * 4 + 3] = v.w;
    }
    __syncthreads();

    // store: 64 o-rows x 8 chunks (8 halves along h) = 512 slots, 2 iters
#pragma unroll
    for (int it = 0; it < 2; ++it) {
        int slot  = tid + it * 256;
        int o     = slot & 63;
        int chunk = slot >> 6;             // 0..7
        __half2 hh[4];
#pragma unroll
        for (int j = 0; j < 4; ++j)
            hh[j] = __floats2half2_rn(t[chunk * 8 + 2 * j][o],
                                      t[chunk * 8 + 2 * j + 1][o]);
        size_t row = ((size_t)g * DOUT + o0 + o) * DHID + h0;
        *reinterpret_cast<uint4*>(&g_wD[row + chunk * 8]) =
            make_uint4(*reinterpret_cast<uint32_t*>(&hh[0]),
                       *reinterpret_cast<uint32_t*>(&hh[1]),
                       *reinterpret_cast<uint32_t*>(&hh[2]),
                       *reinterpret_cast<uint32_t*>(&hh[3]));
    }
}

__global__ void prep_x(const float* __restrict__ x) {
    size_t i = (size_t)blockIdx.x * blockDim.x + threadIdx.x;
    float4 v = reinterpret_cast<const float4*>(x)[i];
    __half2 a = __floats2half2_rn(v.x, v.y);
    __half2 b = __floats2half2_rn(v.z, v.w);
    uint2 o;
    o.x = *reinterpret_cast<uint32_t*>(&a);
    o.y = *reinterpret_cast<uint32_t*>(&b);
    reinterpret_cast<uint2*>(g_x16)[i] = o;
}

// ---------------- GEMM (round-6 proven, byte-for-byte) ----------------
// CTA tile M=128 x N=128, 256 threads (8 warps, 2x4), warp tile 64x32.
// K-step 64, 3-stage cp.async pipeline, 2 CTAs/SM.
#define A_BYTES   (128u * 128u)           // 16384
#define B_BYTES   (128u * 128u)           // 16384
#define STAGE_B   (A_BYTES + B_BYTES)     // 32768
#define SMEM_BYTES (3u * STAGE_B)         // 98304 per CTA -> 192KB for 2 CTAs

static __device__ __forceinline__ void load_stage(uint32_t sb, int s,
        const __half* __restrict__ A, int lda,
        const __half* __restrict__ B, int ldb, int k0, int tid) {
    uint32_t abase = sb + (uint32_t)s * STAGE_B;
#pragma unroll
    for (int i = 0; i < 4; ++i) {                 // A: 128 rows x 8 chunks(16B)
        int id = tid + (i << 8);
        int r = id >> 3, c = id & 7;
        uint32_t dst = abase + (uint32_t)r * 128u + (uint32_t)(((c ^ (r & 7)) << 4));
        CP_ASYNC16(dst, A + (size_t)r * lda + k0 + c * 8);
    }
    uint32_t bbase = abase + A_BYTES;
#pragma unroll
    for (int i = 0; i < 4; ++i) {                 // B: 128 rows x 8 chunks
        int id = tid + (i << 8);
        int r = id >> 3, c = id & 7;
        uint32_t dst = bbase + (uint32_t)r * 128u + (uint32_t)(((c ^ (r & 7)) << 4));
        CP_ASYNC16(dst, B + (size_t)r * ldb + k0 + c * 8);
    }
}

template<bool PHASE1>
__global__ __launch_bounds__(256, 2) void gemm_kernel(float* __restrict__ outp) {
    constexpr int KTOT = PHASE1 ? DIN : DHID;
    constexpr int NC   = KTOT / 64;
    constexpr int LDA  = NG * KTOT;

    extern __shared__ __align__(1024) char smem[];
    uint32_t sb = smem_u32(smem);
    int tid  = threadIdx.x;
    int wid  = tid >> 5;
    int lane = tid & 31;
    int wm   = wid >> 2;          // 0..1  (64-row block)
    int wn   = wid & 3;           // 0..3  (32-col block)
    int m0   = blockIdx.x * 128;
    int g    = blockIdx.z;

    const __half* Abase = (PHASE1 ? g_x16 : g_hid)
                        + (size_t)m0 * LDA + (size_t)g * KTOT;
    const __half* Bbase = (PHASE1 ? g_wA : g_wD)
                        + (size_t)g * (PHASE1 ? (size_t)2 * DHID * DIN : (size_t)DOUT * DHID)
                        + (size_t)blockIdx.y * 128 * KTOT;

    // Precomputed swizzled ldmatrix offsets: addr = stagebase + (pre ^ (ch<<4))
    uint32_t preA[4], preB[2];
    {
        int rsel = lane & 15;
        int hi   = (lane >> 4) << 4;
#pragma unroll
        for (int mt = 0; mt < 4; ++mt) {
            int row = wm * 64 + mt * 16 + rsel;
            preA[mt] = (uint32_t)row * 128u + (uint32_t)(((row & 7) << 4) ^ hi);
        }
#pragma unroll
        for (int nt = 0; nt < 2; ++nt) {
            int row = wn * 32 + nt * 16 + rsel;
            preB[nt] = (uint32_t)row * 128u + (uint32_t)(((row & 7) << 4) ^ hi);
        }
    }

    float acc[4][4][4];
#pragma unroll
    for (int a = 0; a < 4; ++a)
#pragma unroll
        for (int b = 0; b < 4; ++b)
#pragma unroll
            for (int c = 0; c < 4; ++c) acc[a][b][c] = 0.f;

    load_stage(sb, 0, Abase, LDA, Bbase, KTOT, 0, tid);
    CP_COMMIT();
    load_stage(sb, 1, Abase, LDA, Bbase, KTOT, 64, tid);
    CP_COMMIT();

    int st = 0;
#pragma unroll 1
    for (int c = 0; c < NC; ++c) {
        CP_WAIT1();
        __syncthreads();
        uint32_t abase = sb + (uint32_t)st * STAGE_B;
        uint32_t bbase = abase + A_BYTES;

        if (c + 2 < NC) {
            int st2 = (st == 0) ? 2 : st - 1;
            load_stage(sb, st2, Abase, LDA, Bbase, KTOT, (c + 2) * 64, tid);
        }
        CP_COMMIT();

#pragma unroll
        for (int kk = 0; kk < 4; ++kk) {
            uint32_t x = (uint32_t)(kk << 5);     // ch = 2*kk -> (ch<<4)
            uint32_t af[4][4], bf[2][4];
#pragma unroll
            for (int mt = 0; mt < 4; ++mt) ldsm4(af[mt], abase + (preA[mt] ^ x));
#pragma unroll
            for (int nt = 0; nt < 2; ++nt) ldsm4(bf[nt], bbase + (preB[nt] ^ x));
#pragma unroll
            for (int mt = 0; mt < 4; ++mt)
#pragma unroll
                for (int n8 = 0; n8 < 4; ++n8)
                    mma16816(acc[mt][n8], af[mt],
                             bf[n8 >> 1][n8 & 1], bf[n8 >> 1][2 + (n8 & 1)]);
        }
        st = (st == 2) ? 0 : st + 1;
    }

    // ---- epilogue ----
    if constexpr (PHASE1) {
        __syncthreads();
        __half* sh = reinterpret_cast<__half*>(smem);   // staging [128][72]
#pragma unroll
        for (int mt = 0; mt < 4; ++mt)
#pragma unroll
            for (int n8 = 0; n8 < 4; ++n8) {
                int r0 = wm * 64 + mt * 16 + (lane >> 2);
                int hl = wn * 16 + n8 * 4 + (lane & 3);
                float* cc = acc[mt][n8];
                float gv0 = cc[0], uv0 = cc[1];
                float gv1 = cc[2], uv1 = cc[3];
                float h0 = uv0 * gv0 / (1.f + __expf(-gv0));
                float h1 = uv1 * gv1 / (1.f + __expf(-gv1));
                sh[(size_t)r0 * 72 + hl]       = __float2half(h0);
                sh[(size_t)(r0 + 8) * 72 + hl] = __float2half(h1);
            }
        __syncthreads();
        // copy out: 128 rows x 64 halves
        __half* optr = g_hid + (size_t)m0 * (NG * DHID) + (size_t)g * DHID
                     + (size_t)blockIdx.y * 64;
#pragma unroll
        for (int p = 0; p < 4; ++p) {
            int row = (tid >> 3) + p * 32;
            int ch  = tid & 7;
            uint4 v = *reinterpret_cast<uint4*>(sh + (size_t)row * 72 + ch * 8);
            *reinterpret_cast<uint4*>(optr + (size_t)row * (NG * DHID) + ch * 8) = v;
        }
    } else {
#pragma unroll
        for (int mt = 0; mt < 4; ++mt)
#pragma unroll
            for (int n8 = 0; n8 < 4; ++n8) {
                int r0  = wm * 64 + mt * 16 + (lane >> 2);
                int col = blockIdx.y * 128 + wn * 32 + n8 * 8 + (lane & 3) * 2;
                float* cc = acc[mt][n8];
                float* p0 = outp + ((size_t)(m0 + r0) * NG + g) * DOUT + col;
                float* p1 = outp + ((size_t)(m0 + r0 + 8) * NG + g) * DOUT + col;
                *reinterpret_cast<float2*>(p0) = make_float2(cc[0], cc[1]);
                *reinterpret_cast<float2*>(p1) = make_float2(cc[2], cc[3]);
            }
    }
}

// ---------------- launch ----------------
extern "C" void kernel_launch(void* const* d_in, const int* in_sizes, int n_in,
                              void* d_out, int out_size) {
    (void)in_sizes; (void)n_in; (void)out_size;
    const float* x  = (const float*)d_in[0];
    const float* gw = (const float*)d_in[1];
    const float* uw = (const float*)d_in[2];
    const float* dw = (const float*)d_in[3];
    float* out = (float*)d_out;

    cudaFuncSetAttribute(gemm_kernel<true>,  cudaFuncAttributeMaxDynamicSharedMemorySize, SMEM_BYTES);
    cudaFuncSetAttribute(gemm_kernel<false>, cudaFuncAttributeMaxDynamicSharedMemorySize, SMEM_BYTES);

    prep_gateup<<<dim3(DIN / 64, DHID / 32, NG), 256>>>(gw, uw);
    prep_down<<<dim3(DHID / 64, DOUT / 64, NG), 256>>>(dw);
    prep_x<<<65536, 256>>>(x);

    // GEMM1: grid 16 m-tiles x 32 n-tiles x 32 groups
    gemm_kernel<true><<<dim3(16, 32, NG), 256, SMEM_BYTES>>>(out);
    // GEMM2: grid 16 m-tiles x 8 n-tiles x 32 groups
    gemm_kernel<false><<<dim3(16, 8, NG), 256, SMEM_BYTES>>>(out);
}